// round 9
// baseline (speedup 1.0000x reference)
#include <cuda_runtime.h>
#include <cuda_bf16.h>
#include <math.h>

// encoded: (8, 64, 256, 256) f32, masks: (8,1,256,256) i32 (0..32)
// W1: (128,32), b1: (32,), W2: (32,4), b2: (4,)
// out: vectors (8,32,64) ++ connections (8,4,32,32)

#define BATCH 8
#define FDIM 64
#define HW 65536
#define SEGS 33
#define NOBJ 32

__device__ unsigned char g_mask8[BATCH * HW];
__device__ int g_cnt[BATCH];   // zero-initialized; self-resetting per invocation

// Epilogue smem overlay (reuses accumulator buffer; 29.6KB < 67.5KB)
struct EpiShared {
    float sW1[128 * 32];
    float sV[32][64];
    float sA[32][SEGS];
    float sB[32][SEGS];
    float sW2[128];
    float sb1[32];
    float sb2[4];
};

// ---------------------------------------------------------------------------
// K0: pack int32 masks -> uint8.
// ---------------------------------------------------------------------------
__global__ __launch_bounds__(256) void pack_mask_kernel(const int* __restrict__ masks)
{
    int i = blockIdx.x * blockDim.x + threadIdx.x;
    int4 v = ((const int4*)masks)[i];
    unsigned int o = (v.x & 0xff) | ((v.y & 0xff) << 8) |
                     ((v.z & 0xff) << 16) | (v.w << 24);
    ((unsigned int*)g_mask8)[i] = o;
}

// ---------------------------------------------------------------------------
// K1: fused segment-max + per-batch MLP epilogue.
// 256 blocks x 256 threads, 2 f-planes per block (R3 core, measured best).
// __launch_bounds__(256,3): cap regs at ~84 so the hot loop keeps 3 blocks/SM;
// epilogue spills (if any) are confined to the rare last-block path.
// ---------------------------------------------------------------------------
__global__ __launch_bounds__(256, 3) void fused_kernel(
    const float* __restrict__ enc,
    const float* __restrict__ W1, const float* __restrict__ b1,
    const float* __restrict__ W2, const float* __restrict__ b2,
    float* __restrict__ vec_out, float* __restrict__ conn)
{
    extern __shared__ char smem_raw[];
    float2* acc2 = (float2*)smem_raw;            // SEGS*256 float2 = 67584 B

    const int bf = blockIdx.x;                   // 0..255
    const int b  = bf >> 5;
    const int f0 = bf & 31;                      // planes f0, f0+32

    const int t = threadIdx.x;
    const float NEG_INF = __int_as_float(0xff800000);
#pragma unroll
    for (int s = 0; s < SEGS; s++) acc2[s * 256 + t] = make_float2(NEG_INF, NEG_INF);

    const float4* p0 = (const float4*)(enc + ((size_t)b * FDIM + f0) * HW);
    const float4* p1 = (const float4*)(enc + ((size_t)b * FDIM + f0 + 32) * HW);
    const uchar4* m4 = (const uchar4*)(g_mask8 + (size_t)b * HW);

    float2* ac = acc2 + t;

#pragma unroll 4
    for (int i = 0; i < 64; i++) {
        int idx = i * 256 + t;
        float4 v0 = p0[idx];
        float4 v1 = p1[idx];
        uchar4 m  = m4[idx];
        float2* px = ac + (int)m.x * 256;
        float2* py = ac + (int)m.y * 256;
        float2* pz = ac + (int)m.z * 256;
        float2* pw = ac + (int)m.w * 256;
        float2 a0 = *px; a0.x = fmaxf(a0.x, v0.x); a0.y = fmaxf(a0.y, v1.x); *px = a0;
        float2 a1 = *py; a1.x = fmaxf(a1.x, v0.y); a1.y = fmaxf(a1.y, v1.y); *py = a1;
        float2 a2 = *pz; a2.x = fmaxf(a2.x, v0.z); a2.y = fmaxf(a2.y, v1.z); *pz = a2;
        float2 a3 = *pw; a3.x = fmaxf(a3.x, v0.w); a3.y = fmaxf(a3.y, v1.w); *pw = a3;
    }

    __syncthreads();

    // Column reduce: 8 threads/segment, lane-staggered -> conflict-free.
    {
        const int sidx = t >> 3;                 // segment sidx+1
        const int k    = t & 7;
        const float2* base = acc2 + (sidx + 1) * 256 + k * 32;
        float mx = NEG_INF, my = NEG_INF;
#pragma unroll
        for (int i = 0; i < 32; i++) {
            int j = (i + t) & 31;
            float2 v = base[j];
            mx = fmaxf(mx, v.x);
            my = fmaxf(my, v.y);
        }
        mx = fmaxf(mx, __shfl_down_sync(0xffffffffu, mx, 4, 8));
        mx = fmaxf(mx, __shfl_down_sync(0xffffffffu, mx, 2, 8));
        mx = fmaxf(mx, __shfl_down_sync(0xffffffffu, mx, 1, 8));
        my = fmaxf(my, __shfl_down_sync(0xffffffffu, my, 4, 8));
        my = fmaxf(my, __shfl_down_sync(0xffffffffu, my, 2, 8));
        my = fmaxf(my, __shfl_down_sync(0xffffffffu, my, 1, 8));
        if (k == 0) {
            float* vrow = vec_out + ((size_t)b * NOBJ + sidx) * FDIM;
            vrow[f0]      = mx;
            vrow[f0 + 32] = my;
        }
    }

    // ---- last block of batch b runs the MLP epilogue ----
    __threadfence();
    __syncthreads();

    __shared__ int is_last;
    if (t == 0) {
        int rank = atomicAdd(&g_cnt[b], 1);
        is_last = (rank == NOBJ - 1) ? 1 : 0;
    }
    __syncthreads();
    if (!is_last) return;

    __threadfence();                             // acquire
    EpiShared* es = (EpiShared*)smem_raw;        // acc2 is dead past the sync

    // coalesced float4 stages
    {
        const float4* w4 = (const float4*)W1;
#pragma unroll
        for (int r = 0; r < 4; r++) ((float4*)es->sW1)[r * 256 + t] = w4[r * 256 + t];
        const float* vb = vec_out + (size_t)b * 2048;
        for (int i = t; i < 2048; i += 256)
            es->sV[i >> 6][i & 63] = __ldcg(vb + i);     // bypass L1 (cross-SM data)
        if (t < 128) es->sW2[t] = W2[t];
        if (t < 32)  es->sb1[t] = b1[t];
        if (t < 4)   es->sb2[t] = b2[t];
    }
    __syncthreads();

    // Phase A: sA = V @ W1[:64] + b1 ; sB = V @ W1[64:]
    for (int idx = t; idx < 1024; idx += 256) {
        const int i = idx >> 5;                  // warp-uniform
        const int k = idx & 31;                  // lane
        float accA = es->sb1[k];
        float accB = 0.f;
#pragma unroll 8
        for (int d = 0; d < 64; d++) {
            float v = es->sV[i][d];              // broadcast
            accA += v * es->sW1[d * 32 + k];
            accB += v * es->sW1[(64 + d) * 32 + k];
        }
        es->sA[i][k] = accA;
        es->sB[i][k] = accB;
    }
    __syncthreads();

    // Phase B: connections[b,c,j,i] = sigmoid((sA[i]+sB[j]) . W2[:,c] + b2[c])
    for (int idx = t; idx < 1024; idx += 256) {
        const int i = idx >> 5;
        const int j = idx & 31;
        float o0 = es->sb2[0], o1 = es->sb2[1], o2 = es->sb2[2], o3 = es->sb2[3];
#pragma unroll
        for (int k = 0; k < 32; k++) {
            float h = es->sA[i][k] + es->sB[j][k];
            o0 += h * es->sW2[k * 4 + 0];
            o1 += h * es->sW2[k * 4 + 1];
            o2 += h * es->sW2[k * 4 + 2];
            o3 += h * es->sW2[k * 4 + 3];
        }
        float* cb = conn + (size_t)b * 4096 + j * 32 + i;
        cb[0]    = 1.f / (1.f + __expf(-o0));
        cb[1024] = 1.f / (1.f + __expf(-o1));
        cb[2048] = 1.f / (1.f + __expf(-o2));
        cb[3072] = 1.f / (1.f + __expf(-o3));
    }

    if (t == 0) atomicExch(&g_cnt[b], 0);        // reset for next replay
}

// ---------------------------------------------------------------------------
extern "C" void kernel_launch(void* const* d_in, const int* in_sizes, int n_in,
                              void* d_out, int out_size)
{
    const float* enc   = (const float*)d_in[0];
    const int*   masks = (const int*)  d_in[1];
    const float* W1    = (const float*)d_in[2];
    const float* b1    = (const float*)d_in[3];
    const float* W2    = (const float*)d_in[4];
    const float* b2    = (const float*)d_in[5];

    float* out_f = (float*)d_out;
    float* vectors = out_f;
    float* conn    = out_f + BATCH * NOBJ * FDIM;

    static bool attr_done = false;
    if (!attr_done) {
        cudaFuncSetAttribute(fused_kernel,
                             cudaFuncAttributeMaxDynamicSharedMemorySize,
                             SEGS * 256 * (int)sizeof(float2));
        attr_done = true;
    }

    pack_mask_kernel<<<512, 256>>>(masks);
    fused_kernel<<<BATCH * 32, 256, SEGS * 256 * sizeof(float2)>>>(
        enc, W1, b1, W2, b2, vectors, conn);
}

// round 10
// speedup vs baseline: 1.3743x; 1.3743x over previous
#include <cuda_runtime.h>
#include <cuda_bf16.h>
#include <math.h>

// encoded: (8, 64, 256, 256) f32, masks: (8,1,256,256) i32 (0..32)
// W1: (128,32), b1: (32,), W2: (32,4), b2: (4,)
// out: vectors (8,32,64) ++ connections (8,4,32,32)

#define BATCH 8
#define FDIM 64
#define HW 65536
#define SEGS 33
#define NOBJ 32

__device__ unsigned char g_mask8[BATCH * HW];

// ---------------------------------------------------------------------------
// K0: pack int32 masks -> uint8.
// ---------------------------------------------------------------------------
__global__ __launch_bounds__(256) void pack_mask_kernel(const int* __restrict__ masks)
{
    int i = blockIdx.x * blockDim.x + threadIdx.x;
    int4 v = ((const int4*)masks)[i];
    unsigned int o = (v.x & 0xff) | ((v.y & 0xff) << 8) |
                     ((v.z & 0xff) << 16) | (v.w << 24);
    ((unsigned int*)g_mask8)[i] = o;
}

// ---------------------------------------------------------------------------
// K1: segment max (R6 core + software-pipelined main loop).
// 256 blocks x 256 threads, 2 f-planes per block, packed uchar4 masks,
// conflict-free float2 accumulators acc2[s*256 + t].
// Distance-1 prefetch: next iteration's 3 LDG.128s issue before this
// iteration's smem chain -> ~6 outstanding LDGs per warp.
// ---------------------------------------------------------------------------
__global__ __launch_bounds__(256) void segmax_kernel(
    const float* __restrict__ enc, float* __restrict__ vec_out)
{
    extern __shared__ float2 acc2[];            // SEGS*256 float2 = 67584 B

    const int bf = blockIdx.x;                  // 0..255
    const int b  = bf >> 5;
    const int f0 = bf & 31;                     // planes f0, f0+32

    const int t = threadIdx.x;
    const float NEG_INF = __int_as_float(0xff800000);
#pragma unroll
    for (int s = 0; s < SEGS; s++) acc2[s * 256 + t] = make_float2(NEG_INF, NEG_INF);
    // each thread only touches its own column t -> no sync needed

    const float4* p0 = (const float4*)(enc + ((size_t)b * FDIM + f0) * HW);
    const float4* p1 = (const float4*)(enc + ((size_t)b * FDIM + f0 + 32) * HW);
    const uchar4* m4 = (const uchar4*)(g_mask8 + (size_t)b * HW);

    float2* ac = acc2 + t;

    // ---- software-pipelined loop ----
    int idx = t;
    float4 v0 = p0[idx];
    float4 v1 = p1[idx];
    uchar4 m  = m4[idx];

#pragma unroll 2
    for (int i = 0; i < 63; i++) {
        const int nidx = idx + 256;
        // prefetch next (independent of the smem chain below)
        float4 nv0 = p0[nidx];
        float4 nv1 = p1[nidx];
        uchar4 nm  = m4[nidx];

        // process current
        float2* px = ac + (int)m.x * 256;
        float2* py = ac + (int)m.y * 256;
        float2* pz = ac + (int)m.z * 256;
        float2* pw = ac + (int)m.w * 256;
        float2 a0 = *px; a0.x = fmaxf(a0.x, v0.x); a0.y = fmaxf(a0.y, v1.x); *px = a0;
        float2 a1 = *py; a1.x = fmaxf(a1.x, v0.y); a1.y = fmaxf(a1.y, v1.y); *py = a1;
        float2 a2 = *pz; a2.x = fmaxf(a2.x, v0.z); a2.y = fmaxf(a2.y, v1.z); *pz = a2;
        float2 a3 = *pw; a3.x = fmaxf(a3.x, v0.w); a3.y = fmaxf(a3.y, v1.w); *pw = a3;

        v0 = nv0; v1 = nv1; m = nm; idx = nidx;
    }
    // epilogue iteration
    {
        float2* px = ac + (int)m.x * 256;
        float2* py = ac + (int)m.y * 256;
        float2* pz = ac + (int)m.z * 256;
        float2* pw = ac + (int)m.w * 256;
        float2 a0 = *px; a0.x = fmaxf(a0.x, v0.x); a0.y = fmaxf(a0.y, v1.x); *px = a0;
        float2 a1 = *py; a1.x = fmaxf(a1.x, v0.y); a1.y = fmaxf(a1.y, v1.y); *py = a1;
        float2 a2 = *pz; a2.x = fmaxf(a2.x, v0.z); a2.y = fmaxf(a2.y, v1.z); *pz = a2;
        float2 a3 = *pw; a3.x = fmaxf(a3.x, v0.w); a3.y = fmaxf(a3.y, v1.w); *pw = a3;
    }

    __syncthreads();

    // Column reduce: 8 threads/segment, lane-staggered -> conflict-free.
    {
        const int sidx = t >> 3;                // segment sidx+1
        const int k    = t & 7;
        const float2* base = acc2 + (sidx + 1) * 256 + k * 32;
        float mx = NEG_INF, my = NEG_INF;
#pragma unroll
        for (int i = 0; i < 32; i++) {
            int j = (i + t) & 31;
            float2 v = base[j];
            mx = fmaxf(mx, v.x);
            my = fmaxf(my, v.y);
        }
        mx = fmaxf(mx, __shfl_down_sync(0xffffffffu, mx, 4, 8));
        mx = fmaxf(mx, __shfl_down_sync(0xffffffffu, mx, 2, 8));
        mx = fmaxf(mx, __shfl_down_sync(0xffffffffu, mx, 1, 8));
        my = fmaxf(my, __shfl_down_sync(0xffffffffu, my, 4, 8));
        my = fmaxf(my, __shfl_down_sync(0xffffffffu, my, 2, 8));
        my = fmaxf(my, __shfl_down_sync(0xffffffffu, my, 1, 8));
        if (k == 0) {
            float* vrow = vec_out + ((size_t)b * NOBJ + sidx) * FDIM;
            vrow[f0]      = mx;
            vrow[f0 + 32] = my;
        }
    }
}

// ---------------------------------------------------------------------------
// K2: pair MLP — 32 blocks (8 batches x 4 i-tiles), 256 threads (R6, measured).
// ---------------------------------------------------------------------------
__global__ __launch_bounds__(256) void pair_mlp_kernel(
    const float* __restrict__ vec, const float* __restrict__ W1,
    const float* __restrict__ b1, const float* __restrict__ W2,
    const float* __restrict__ b2, float* __restrict__ conn)
{
    const int b    = blockIdx.x >> 2;
    const int tile = blockIdx.x & 3;        // i in [tile*8, tile*8+8)
    const int t    = threadIdx.x;

    __shared__ float sW1[128 * 32];
    __shared__ float sV[32][64];
    __shared__ float sA[8][SEGS];
    __shared__ float sB[32][SEGS];
    __shared__ float sW2[128];
    __shared__ float sb1[32];
    __shared__ float sb2[4];

    {
        const float4* w4 = (const float4*)W1;
#pragma unroll
        for (int r = 0; r < 4; r++) ((float4*)sW1)[r * 256 + t] = w4[r * 256 + t];
        const float4* v4 = (const float4*)(vec + (size_t)b * 2048);
#pragma unroll
        for (int r = 0; r < 2; r++) {
            int idx = r * 256 + t;
            ((float4*)sV)[idx] = v4[idx];
        }
        if (t < 128) sW2[t] = W2[t];
        if (t < 32)  sb1[t] = b1[t];
        if (t < 4)   sb2[t] = b2[t];
    }
    __syncthreads();

    {
        const int il = t >> 5;              // 0..7 (warp-uniform)
        const int k  = t & 31;              // lane
        const int i  = tile * 8 + il;
        float a = sb1[k];
#pragma unroll 8
        for (int d = 0; d < 64; d++)
            a += sV[i][d] * sW1[d * 32 + k];
        sA[il][k] = a;

#pragma unroll
        for (int r = 0; r < 4; r++) {
            const int j = r * 8 + il;
            float bb = 0.f;
#pragma unroll 8
            for (int d = 0; d < 64; d++)
                bb += sV[j][d] * sW1[(64 + d) * 32 + k];
            sB[j][k] = bb;
        }
    }
    __syncthreads();

    {
        const int il = t >> 5;
        const int j  = t & 31;
        const int i  = tile * 8 + il;
        float o0 = sb2[0], o1 = sb2[1], o2 = sb2[2], o3 = sb2[3];
#pragma unroll
        for (int k = 0; k < 32; k++) {
            float h = sA[il][k] + sB[j][k];
            o0 += h * sW2[k * 4 + 0];
            o1 += h * sW2[k * 4 + 1];
            o2 += h * sW2[k * 4 + 2];
            o3 += h * sW2[k * 4 + 3];
        }
        float* cb = conn + (size_t)b * 4096 + j * 32 + i;
        cb[0]    = 1.f / (1.f + __expf(-o0));
        cb[1024] = 1.f / (1.f + __expf(-o1));
        cb[2048] = 1.f / (1.f + __expf(-o2));
        cb[3072] = 1.f / (1.f + __expf(-o3));
    }
}

// ---------------------------------------------------------------------------
extern "C" void kernel_launch(void* const* d_in, const int* in_sizes, int n_in,
                              void* d_out, int out_size)
{
    const float* enc   = (const float*)d_in[0];
    const int*   masks = (const int*)  d_in[1];
    const float* W1    = (const float*)d_in[2];
    const float* b1    = (const float*)d_in[3];
    const float* W2    = (const float*)d_in[4];
    const float* b2    = (const float*)d_in[5];

    float* out_f = (float*)d_out;
    float* vectors = out_f;
    float* conn    = out_f + BATCH * NOBJ * FDIM;

    static bool attr_done = false;
    if (!attr_done) {
        cudaFuncSetAttribute(segmax_kernel,
                             cudaFuncAttributeMaxDynamicSharedMemorySize,
                             SEGS * 256 * (int)sizeof(float2));
        attr_done = true;
    }

    pack_mask_kernel<<<512, 256>>>(masks);
    segmax_kernel<<<BATCH * 32, 256, SEGS * 256 * sizeof(float2)>>>(enc, vectors);
    pair_mlp_kernel<<<BATCH * 4, 256>>>(vectors, W1, b1, W2, b2, conn);
}